// round 16
// baseline (speedup 1.0000x reference)
#include <cuda_runtime.h>
#include <cuda_fp16.h>
#include <math.h>
#include <stdint.h>

#define NT 512
#define RB 64

// smem byte offsets
#define A0_OFF   0          // X0 [64][136] fp16
#define A1_OFF   17408      // X1
#define A2_OFF   34816      // X2
#define W0_OFF   52224      // weight [128][136] fp16
#define W1_OFF   87040
#define UF_OFF   121856     // u fp32 [3][64][128] = 98304 B
#define SM_TOTAL 220160

// pre-rounded padded weights: 7 tiles of [128 n][136 k] fp16
// tiles: 0=U, 1=V, 2=W1[:, :128], 3=W1[:, 128:], 4..6=W2 row-chunks
__device__ __align__(16) __half g_wh[7 * 128 * 136];

__device__ __forceinline__ uint32_t s2u(const void* p) {
    uint32_t a;
    asm("{ .reg .u64 t; cvta.to.shared.u64 t, %1; cvt.u32.u64 %0, t; }" : "=r"(a) : "l"(p));
    return a;
}

#define LDSM4(d, a) \
    asm volatile("ldmatrix.sync.aligned.m8n8.x4.shared.b16 {%0,%1,%2,%3}, [%4];" \
                 : "=r"((d)[0]), "=r"((d)[1]), "=r"((d)[2]), "=r"((d)[3]) : "r"(a))

__device__ __forceinline__ void mma_16816(float* d, const uint32_t a[4],
                                          uint32_t b0, uint32_t b1) {
    asm volatile(
        "mma.sync.aligned.m16n8k16.row.col.f32.f16.f16.f32 "
        "{%0,%1,%2,%3}, {%4,%5,%6,%7}, {%8,%9}, {%0,%1,%2,%3};"
        : "+f"(d[0]), "+f"(d[1]), "+f"(d[2]), "+f"(d[3])
        : "r"(a[0]), "r"(a[1]), "r"(a[2]), "r"(a[3]), "r"(b0), "r"(b1));
}

__device__ __forceinline__ void cp16(uint32_t dst, const void* src) {
    asm volatile("cp.async.cg.shared.global [%0], [%1], 16;"
                 :: "r"(dst), "l"(src) : "memory");
}
#define CP_COMMIT() asm volatile("cp.async.commit_group;" ::: "memory")
#define CP_WAIT0()  asm volatile("cp.async.wait_group 0;" ::: "memory")
#define CP_WAIT1()  asm volatile("cp.async.wait_group 1;" ::: "memory")

// K=128 GEMM, single-pass fp16: acc0 (+)= A x B0 [, acc1 (+)= A x B1]
template <bool DUAL>
__device__ __forceinline__ void gemm1(float* acc0, float* acc1,
                                      uint32_t aH0, uint32_t aH1,
                                      uint32_t b0, uint32_t b1) {
#pragma unroll
    for (int k0 = 0; k0 < 128; k0 += 16) {
        const uint32_t ko = (uint32_t)k0 * 2;
        uint32_t fa[2][4], fb0[4];
        LDSM4(fa[0], aH0 + ko);
        LDSM4(fa[1], aH1 + ko);
        LDSM4(fb0, b0 + ko);
#pragma unroll
        for (int mt = 0; mt < 2; mt++)
#pragma unroll
            for (int nt = 0; nt < 2; nt++)
                mma_16816(acc0 + mt * 8 + nt * 4, fa[mt], fb0[nt * 2], fb0[nt * 2 + 1]);
        if (DUAL) {
            uint32_t fb1[4];
            LDSM4(fb1, b1 + ko);
#pragma unroll
            for (int mt = 0; mt < 2; mt++)
#pragma unroll
                for (int nt = 0; nt < 2; nt++)
                    mma_16816(acc1 + mt * 8 + nt * 4, fa[mt], fb1[nt * 2], fb1[nt * 2 + 1]);
        }
    }
}

// ---------------------------------------------------------------------------
__global__ void prep_kernel(const float* __restrict__ U, const float* __restrict__ V,
                            const float* __restrict__ W1, const float* __restrict__ W2) {
    int idx = blockIdx.x * blockDim.x + threadIdx.x;
    if (idx >= 7 * 16384) return;
    int t = idx >> 14;
    int n = (idx >> 7) & 127;
    int k = idx & 127;
    float val;
    if (t == 0)      val = U[n * 128 + k];
    else if (t == 1) val = V[n * 128 + k];
    else if (t == 2) val = W1[n * 256 + k];
    else if (t == 3) val = W1[n * 256 + 128 + k];
    else             val = W2[((t - 4) * 128 + n) * 128 + k];
    g_wh[t * 17408 + n * 136 + k] = __float2half_rn(val);
}

// ---------------------------------------------------------------------------
__global__ __launch_bounds__(NT, 1)
void update_mma_kernel(const float* __restrict__ vec, const float* __restrict__ sca,
                       const float* __restrict__ b1g, const float* __restrict__ b2g,
                       float* __restrict__ out, int nrows) {
    extern __shared__ char sm[];
    const uint32_t smb = s2u(sm);
    float* Uf = (float*)(sm + UF_OFF);  // u fp32 [3][64][128]

    const int tid = threadIdx.x;
    const int lane = tid & 31;
    const int w = tid >> 5;
    const int wm = w & 1;    // M band (0/1)
    const int wn = w >> 1;   // N band (0..7)
    const int row0 = blockIdx.x * RB;

    // ldmatrix per-thread byte offsets (within a [.][136]-half region)
    const uint32_t aoff0 = ((wm * 32 + (lane & 7) + ((lane >> 3) & 1) * 8) * 136
                            + ((lane >> 4) & 1) * 8) * 2;
    const uint32_t aoff1 = aoff0 + 16 * 136 * 2;
    const uint32_t boff  = ((wn * 16 + ((lane >> 4) & 1) * 8 + (lane & 7)) * 136
                            + ((lane >> 3) & 1) * 8) * 2;

    const uint32_t B0 = smb + W0_OFF + boff, B1 = smb + W1_OFF + boff;

    // fragment ownership bases
    const int rbase = wm * 32 + (lane >> 2);
    const int cbase = wn * 16 + (lane & 3) * 2;

#define POS_LOOP(body) \
    _Pragma("unroll") for (int mt = 0; mt < 2; mt++) \
    _Pragma("unroll") for (int nt = 0; nt < 2; nt++) \
    _Pragma("unroll") for (int jj = 0; jj < 4; jj++) { \
        const int idx = mt * 8 + nt * 4 + jj; \
        const int row = rbase + mt * 16 + (jj >> 1) * 8; \
        const int col = cbase + nt * 8 + (jj & 1); \
        body \
    }

    // weight tile t (34816 B) -> region, one cp.async group
    auto cpa_w = [&](uint32_t dstOff, int t) {
        const uint4* sh = (const uint4*)(g_wh + t * 17408);
        for (int i = tid; i < 2176; i += NT) cp16(smb + dstOff + i * 16, sh + i);
        CP_COMMIT();
    };

    float pf[16];
    auto prefetch_vec = [&](int i) {
#pragma unroll
        for (int q = 0; q < 16; q++) {
            int e = tid + q * NT;
            int r = e >> 7, c = e & 127;
            pf[q] = __ldg(vec + (size_t)(row0 + r) * 384 + c * 3 + i);
        }
    };
    auto prefetch_sca = [&]() {
#pragma unroll
        for (int q = 0; q < 16; q++) {
            int e = tid + q * NT;
            int r = e >> 7, c = e & 127;
            pf[q] = __ldg(sca + (size_t)(row0 + r) * 128 + c);
        }
    };
    auto sts_pf = [&](uint32_t bufOff) {
        __half* dst = (__half*)(sm + bufOff);
#pragma unroll
        for (int q = 0; q < 16; q++) {
            int e = tid + q * NT;
            int r = e >> 7, c = e & 127;
            dst[r * 136 + c] = __float2half_rn(pf[q]);
        }
    };

    // ---- init: weights U,V in flight; stage X0,X1,X2 upfront ----
    cpa_w(W0_OFF, 0);   // G0: U
    cpa_w(W1_OFF, 1);   // G1: V
    prefetch_vec(0); sts_pf(A0_OFF);
    prefetch_vec(1); sts_pf(A1_OFF);
    prefetch_vec(2); sts_pf(A2_OFF);
    prefetch_sca();     // scalar LDGs fly under phase-1 GEMMs
    CP_WAIT0();
    __syncthreads();

    // ---- phase 1: three dual GEMMs, no intervening barriers ----
    float dotv[16], ssq[16];
#pragma unroll
    for (int j = 0; j < 16; j++) { dotv[j] = 0.0f; ssq[j] = 1e-8f; }

    const uint32_t abuf[3] = {A0_OFF, A1_OFF, A2_OFF};
#pragma unroll
    for (int i = 0; i < 3; i++) {
        const uint32_t AH0 = smb + abuf[i] + aoff0;
        const uint32_t AH1 = smb + abuf[i] + aoff1;
        float uacc[16], vacc[16];
#pragma unroll
        for (int j = 0; j < 16; j++) { uacc[j] = 0.0f; vacc[j] = 0.0f; }
        gemm1<true>(uacc, vacc, AH0, AH1, B0, B1);
#pragma unroll
        for (int j = 0; j < 16; j++) {
            dotv[j] += uacc[j] * vacc[j];
            ssq[j]  += vacc[j] * vacc[j];
        }
        POS_LOOP( Uf[(i << 13) + (row << 7) + col] = uacc[idx]; )
    }
    __syncthreads();    // A buffers + W0/W1 dead

    // ---- phase 2: h = silu([s|vnorm] @ W1^T + b1) ----
    cpa_w(W0_OFF, 2);   // G2: W1a
    cpa_w(W1_OFF, 3);   // G3: W1b
    sts_pf(A0_OFF);     // A0 = scalar tile (from prefetched regs)
    {                   // A1 = vnorm tile
        __half* dst = (__half*)(sm + A1_OFF);
        POS_LOOP( dst[row * 136 + col] = __float2half_rn(sqrtf(ssq[idx])); )
    }
    CP_WAIT1();         // G2 (W1a) landed; G3 flying
    __syncthreads();
    float hacc[16];
#pragma unroll
    for (int j = 0; j < 16; j++) hacc[j] = 0.0f;
    gemm1<false>(hacc, hacc, smb + A0_OFF + aoff0, smb + A0_OFF + aoff1, B0, 0);
    CP_WAIT0();         // G3 (W1b) landed
    __syncthreads();    // all warps past W0-read
    cpa_w(W0_OFF, 4);   // G4: W2a (flies under next GEMM)
    gemm1<false>(hacc, hacc, smb + A1_OFF + aoff0, smb + A1_OFF + aoff1, B1, 0);
    __syncthreads();    // A0 free (all past scalar GEMM), W1 free
    {                   // A0 = silu(h + b1)
        __half* dst = (__half*)(sm + A0_OFF);
        POS_LOOP(
            float x = hacc[idx] + __ldg(b1g + col);
            dst[row * 136 + col] = __float2half_rn(x / (1.0f + __expf(-x)));
        )
    }
    cpa_w(W1_OFF, 5);   // G5: W2b
    CP_WAIT0();         // G4, G5 landed
    __syncthreads();

    // ---- phase 3: a,b (dual), then c ----
    const uint32_t HA0 = smb + A0_OFF + aoff0, HA1 = smb + A0_OFF + aoff1;
    float aacc[16], bacc[16];
#pragma unroll
    for (int j = 0; j < 16; j++) { aacc[j] = 0.0f; bacc[j] = 0.0f; }
    gemm1<true>(aacc, bacc, HA0, HA1, B0, B1);
    float av[16], bv[16];
    POS_LOOP(
        av[idx] = aacc[idx] + __ldg(b2g + col);
        bv[idx] = bacc[idx] + __ldg(b2g + 128 + col);
    )
    __syncthreads();    // W0 dead
    cpa_w(W0_OFF, 6);   // G6: W2c
    CP_WAIT0();
    __syncthreads();
    float cacc[16];
#pragma unroll
    for (int j = 0; j < 16; j++) cacc[j] = 0.0f;
    gemm1<false>(cacc, cacc, HA0, HA1, B0, 0);

    // ---- epilogue: direct global writes from fragment owners ----
    // delta_s = b + c*dot  (float2, 8B-aligned)
    {
        float* out_ds = out + (size_t)nrows * 384;
#pragma unroll
        for (int mt = 0; mt < 2; mt++)
#pragma unroll
            for (int nt = 0; nt < 2; nt++)
#pragma unroll
                for (int j2 = 0; j2 < 2; j2++) {
                    const int i0 = mt * 8 + nt * 4 + j2 * 2;
                    const int row = rbase + mt * 16 + j2 * 8;
                    const int c = cbase + nt * 8;
                    float c0 = cacc[i0]     + __ldg(b2g + 256 + c);
                    float c1 = cacc[i0 + 1] + __ldg(b2g + 256 + c + 1);
                    float2 d = make_float2(bv[i0] + c0 * dotv[i0],
                                           bv[i0 + 1] + c1 * dotv[i0 + 1]);
                    *(float2*)(out_ds + (size_t)(row0 + row) * 128 + c) = d;
                }
    }
    // delta_v = u (fp32) * a  (3x float2 per (row, col-pair))
#pragma unroll
    for (int mt = 0; mt < 2; mt++)
#pragma unroll
        for (int nt = 0; nt < 2; nt++)
#pragma unroll
            for (int j2 = 0; j2 < 2; j2++) {
                const int i0 = mt * 8 + nt * 4 + j2 * 2;
                const int row = rbase + mt * 16 + j2 * 8;
                const int c = cbase + nt * 8;
                float a0 = av[i0], a1 = av[i0 + 1];
                float u0c = Uf[(0 << 13) + (row << 7) + c];
                float u1c = Uf[(1 << 13) + (row << 7) + c];
                float u2c = Uf[(2 << 13) + (row << 7) + c];
                float u0d = Uf[(0 << 13) + (row << 7) + c + 1];
                float u1d = Uf[(1 << 13) + (row << 7) + c + 1];
                float u2d = Uf[(2 << 13) + (row << 7) + c + 1];
                float* op = out + (size_t)(row0 + row) * 384 + (size_t)c * 3;
                ((float2*)op)[0] = make_float2(u0c * a0, u1c * a0);
                ((float2*)op)[1] = make_float2(u2c * a0, u0d * a1);
                ((float2*)op)[2] = make_float2(u1d * a1, u2d * a1);
            }
#undef POS_LOOP
}

// ---------------------------------------------------------------------------
extern "C" void kernel_launch(void* const* d_in, const int* in_sizes, int n_in,
                              void* d_out, int out_size) {
    const float* vec = (const float*)d_in[0];  // [N, C, 3]
    const float* sca = (const float*)d_in[1];  // [N, C]
    const float* U   = (const float*)d_in[2];  // [C, C]
    const float* V   = (const float*)d_in[3];  // [C, C]
    const float* W1  = (const float*)d_in[4];  // [C, 2C]
    const float* b1  = (const float*)d_in[5];  // [C]
    const float* W2  = (const float*)d_in[6];  // [3C, C]
    const float* b2  = (const float*)d_in[7];  // [3C]
    float* out = (float*)d_out;

    int nrows = in_sizes[0] / 384;
    int nblocks = nrows / RB;

    prep_kernel<<<448, 256>>>(U, V, W1, W2);

    cudaFuncSetAttribute(update_mma_kernel,
                         cudaFuncAttributeMaxDynamicSharedMemorySize, SM_TOTAL);
    update_mma_kernel<<<nblocks, NT, SM_TOTAL>>>(vec, sca, b1, b2, out, nrows);
}

// round 17
// speedup vs baseline: 1.0438x; 1.0438x over previous
#include <cuda_runtime.h>
#include <cuda_fp16.h>
#include <math.h>
#include <stdint.h>

#define NT 512
#define RB 64

// smem byte offsets
#define A0_OFF   0          // X0 [64][136] fp16
#define A1_OFF   17408      // X1 ; phase-3: W2c region = [A1, A1+34816)
#define A2_OFF   34816      // X2
#define W0_OFF   52224      // weight [128][136] fp16
#define W1_OFF   87040
#define UF_OFF   121856     // u fp32 [3][64][128] = 98304 B
#define SM_TOTAL 220160

// pre-rounded padded weights: 7 tiles of [128 n][136 k] fp16
// tiles: 0=U, 1=V, 2=W1[:, :128], 3=W1[:, 128:], 4..6=W2 row-chunks
__device__ __align__(16) __half g_wh[7 * 128 * 136];

__device__ __forceinline__ uint32_t s2u(const void* p) {
    uint32_t a;
    asm("{ .reg .u64 t; cvta.to.shared.u64 t, %1; cvt.u32.u64 %0, t; }" : "=r"(a) : "l"(p));
    return a;
}

#define LDSM4(d, a) \
    asm volatile("ldmatrix.sync.aligned.m8n8.x4.shared.b16 {%0,%1,%2,%3}, [%4];" \
                 : "=r"((d)[0]), "=r"((d)[1]), "=r"((d)[2]), "=r"((d)[3]) : "r"(a))

__device__ __forceinline__ void mma_16816(float* d, const uint32_t a[4],
                                          uint32_t b0, uint32_t b1) {
    asm volatile(
        "mma.sync.aligned.m16n8k16.row.col.f32.f16.f16.f32 "
        "{%0,%1,%2,%3}, {%4,%5,%6,%7}, {%8,%9}, {%0,%1,%2,%3};"
        : "+f"(d[0]), "+f"(d[1]), "+f"(d[2]), "+f"(d[3])
        : "r"(a[0]), "r"(a[1]), "r"(a[2]), "r"(a[3]), "r"(b0), "r"(b1));
}

__device__ __forceinline__ void cp16(uint32_t dst, const void* src) {
    asm volatile("cp.async.cg.shared.global [%0], [%1], 16;"
                 :: "r"(dst), "l"(src) : "memory");
}
#define CP_COMMIT() asm volatile("cp.async.commit_group;" ::: "memory")
#define CP_WAIT0()  asm volatile("cp.async.wait_group 0;" ::: "memory")
#define CP_WAIT1()  asm volatile("cp.async.wait_group 1;" ::: "memory")

// K=128 GEMM, single-pass fp16: acc0 (+)= A x B0 [, acc1 (+)= A x B1]
template <bool DUAL>
__device__ __forceinline__ void gemm1(float* acc0, float* acc1,
                                      uint32_t aH0, uint32_t aH1,
                                      uint32_t b0, uint32_t b1) {
#pragma unroll
    for (int k0 = 0; k0 < 128; k0 += 16) {
        const uint32_t ko = (uint32_t)k0 * 2;
        uint32_t fa[2][4], fb0[4];
        LDSM4(fa[0], aH0 + ko);
        LDSM4(fa[1], aH1 + ko);
        LDSM4(fb0, b0 + ko);
#pragma unroll
        for (int mt = 0; mt < 2; mt++)
#pragma unroll
            for (int nt = 0; nt < 2; nt++)
                mma_16816(acc0 + mt * 8 + nt * 4, fa[mt], fb0[nt * 2], fb0[nt * 2 + 1]);
        if (DUAL) {
            uint32_t fb1[4];
            LDSM4(fb1, b1 + ko);
#pragma unroll
            for (int mt = 0; mt < 2; mt++)
#pragma unroll
                for (int nt = 0; nt < 2; nt++)
                    mma_16816(acc1 + mt * 8 + nt * 4, fa[mt], fb1[nt * 2], fb1[nt * 2 + 1]);
        }
    }
}

// K=128 GEMM, triple-B: acc{0,1,2} (+)= A x B{0,1,2}, A fragments shared
__device__ __forceinline__ void gemm3(float* acc0, float* acc1, float* acc2,
                                      uint32_t aH0, uint32_t aH1,
                                      uint32_t b0, uint32_t b1, uint32_t b2) {
#pragma unroll
    for (int k0 = 0; k0 < 128; k0 += 16) {
        const uint32_t ko = (uint32_t)k0 * 2;
        uint32_t fa[2][4], fb0[4], fb1[4], fb2[4];
        LDSM4(fa[0], aH0 + ko);
        LDSM4(fa[1], aH1 + ko);
        LDSM4(fb0, b0 + ko);
        LDSM4(fb1, b1 + ko);
        LDSM4(fb2, b2 + ko);
#pragma unroll
        for (int mt = 0; mt < 2; mt++)
#pragma unroll
            for (int nt = 0; nt < 2; nt++) {
                mma_16816(acc0 + mt * 8 + nt * 4, fa[mt], fb0[nt * 2], fb0[nt * 2 + 1]);
                mma_16816(acc1 + mt * 8 + nt * 4, fa[mt], fb1[nt * 2], fb1[nt * 2 + 1]);
                mma_16816(acc2 + mt * 8 + nt * 4, fa[mt], fb2[nt * 2], fb2[nt * 2 + 1]);
            }
    }
}

// ---------------------------------------------------------------------------
__global__ void prep_kernel(const float* __restrict__ U, const float* __restrict__ V,
                            const float* __restrict__ W1, const float* __restrict__ W2) {
    int idx = blockIdx.x * blockDim.x + threadIdx.x;
    if (idx >= 7 * 16384) return;
    int t = idx >> 14;
    int n = (idx >> 7) & 127;
    int k = idx & 127;
    float val;
    if (t == 0)      val = U[n * 128 + k];
    else if (t == 1) val = V[n * 128 + k];
    else if (t == 2) val = W1[n * 256 + k];
    else if (t == 3) val = W1[n * 256 + 128 + k];
    else             val = W2[((t - 4) * 128 + n) * 128 + k];
    g_wh[t * 17408 + n * 136 + k] = __float2half_rn(val);
}

// ---------------------------------------------------------------------------
__global__ __launch_bounds__(NT, 1)
void update_mma_kernel(const float* __restrict__ vec, const float* __restrict__ sca,
                       const float* __restrict__ b1g, const float* __restrict__ b2g,
                       float* __restrict__ out, int nrows) {
    extern __shared__ char sm[];
    const uint32_t smb = s2u(sm);
    float* Uf = (float*)(sm + UF_OFF);  // u fp32 [3][64][128]

    const int tid = threadIdx.x;
    const int lane = tid & 31;
    const int w = tid >> 5;
    const int wm = w & 1;    // M band (0/1)
    const int wn = w >> 1;   // N band (0..7)
    const int row0 = blockIdx.x * RB;

    // ldmatrix per-thread byte offsets (within a [.][136]-half region)
    const uint32_t aoff0 = ((wm * 32 + (lane & 7) + ((lane >> 3) & 1) * 8) * 136
                            + ((lane >> 4) & 1) * 8) * 2;
    const uint32_t aoff1 = aoff0 + 16 * 136 * 2;
    const uint32_t boff  = ((wn * 16 + ((lane >> 4) & 1) * 8 + (lane & 7)) * 136
                            + ((lane >> 3) & 1) * 8) * 2;

    const uint32_t B0 = smb + W0_OFF + boff, B1 = smb + W1_OFF + boff;
    const uint32_t B2 = smb + A1_OFF + boff;   // phase-3 W2c region

    // fragment ownership bases
    const int rbase = wm * 32 + (lane >> 2);
    const int cbase = wn * 16 + (lane & 3) * 2;

#define POS_LOOP(body) \
    _Pragma("unroll") for (int mt = 0; mt < 2; mt++) \
    _Pragma("unroll") for (int nt = 0; nt < 2; nt++) \
    _Pragma("unroll") for (int jj = 0; jj < 4; jj++) { \
        const int idx = mt * 8 + nt * 4 + jj; \
        const int row = rbase + mt * 16 + (jj >> 1) * 8; \
        const int col = cbase + nt * 8 + (jj & 1); \
        body \
    }

    // weight tile t (34816 B) -> region, one cp.async group
    auto cpa_w = [&](uint32_t dstOff, int t) {
        const uint4* sh = (const uint4*)(g_wh + t * 17408);
        for (int i = tid; i < 2176; i += NT) cp16(smb + dstOff + i * 16, sh + i);
        CP_COMMIT();
    };

    float pf[16];
    auto prefetch_vec = [&](int i) {
#pragma unroll
        for (int q = 0; q < 16; q++) {
            int e = tid + q * NT;
            int r = e >> 7, c = e & 127;
            pf[q] = __ldg(vec + (size_t)(row0 + r) * 384 + c * 3 + i);
        }
    };
    auto prefetch_sca = [&]() {
#pragma unroll
        for (int q = 0; q < 16; q++) {
            int e = tid + q * NT;
            int r = e >> 7, c = e & 127;
            pf[q] = __ldg(sca + (size_t)(row0 + r) * 128 + c);
        }
    };
    auto sts_pf = [&](uint32_t bufOff) {
        __half* dst = (__half*)(sm + bufOff);
#pragma unroll
        for (int q = 0; q < 16; q++) {
            int e = tid + q * NT;
            int r = e >> 7, c = e & 127;
            dst[r * 136 + c] = __float2half_rn(pf[q]);
        }
    };

    // ---- init: U,V copies fly; stage X0, X1 ----
    cpa_w(W0_OFF, 0);   // G0: U
    cpa_w(W1_OFF, 1);   // G1: V
    prefetch_vec(0); sts_pf(A0_OFF);
    prefetch_vec(1); sts_pf(A1_OFF);
    CP_WAIT0();
    __syncthreads();

    // ---- phase 1 ----
    float dotv[16], ssq[16];
#pragma unroll
    for (int j = 0; j < 16; j++) { dotv[j] = 0.0f; ssq[j] = 1e-8f; }

    prefetch_vec(2);          // X2 LDGs fly under GEMM(X0)
    {
        float uacc[16], vacc[16];
#pragma unroll
        for (int j = 0; j < 16; j++) { uacc[j] = 0.0f; vacc[j] = 0.0f; }
        gemm1<true>(uacc, vacc, smb + A0_OFF + aoff0, smb + A0_OFF + aoff1, B0, B1);
#pragma unroll
        for (int j = 0; j < 16; j++) {
            dotv[j] += uacc[j] * vacc[j];
            ssq[j]  += vacc[j] * vacc[j];
        }
        POS_LOOP( Uf[(0 << 13) + (row << 7) + col] = uacc[idx]; )
    }
    sts_pf(A2_OFF);           // X2 -> A2
    prefetch_sca();           // scalar LDGs fly under GEMM(X1), GEMM(X2)
    __syncthreads();          // A2 visible to all
#pragma unroll
    for (int i = 1; i < 3; i++) {
        const uint32_t ab = (i == 1) ? A1_OFF : A2_OFF;
        float uacc[16], vacc[16];
#pragma unroll
        for (int j = 0; j < 16; j++) { uacc[j] = 0.0f; vacc[j] = 0.0f; }
        gemm1<true>(uacc, vacc, smb + ab + aoff0, smb + ab + aoff1, B0, B1);
#pragma unroll
        for (int j = 0; j < 16; j++) {
            dotv[j] += uacc[j] * vacc[j];
            ssq[j]  += vacc[j] * vacc[j];
        }
        POS_LOOP( Uf[(i << 13) + (row << 7) + col] = uacc[idx]; )
    }
    __syncthreads();          // phase 1 done: A0/A1/W0/W1 free

    // ---- phase 2: h = silu([s|vnorm] @ W1^T + b1) ----
    cpa_w(W0_OFF, 2);         // G2: W1a
    cpa_w(W1_OFF, 3);         // G3: W1b
    sts_pf(A0_OFF);           // A0 = scalar tile
    {                         // A1 = vnorm tile
        __half* dst = (__half*)(sm + A1_OFF);
        POS_LOOP( dst[row * 136 + col] = __float2half_rn(sqrtf(ssq[idx])); )
    }
    CP_WAIT1();               // G2 landed; G3 flying
    __syncthreads();
    float hacc[16];
#pragma unroll
    for (int j = 0; j < 16; j++) hacc[j] = 0.0f;
    gemm1<false>(hacc, hacc, smb + A0_OFF + aoff0, smb + A0_OFF + aoff1, B0, 0);
    CP_WAIT0();               // G3 landed
    __syncthreads();          // all warps past W0 reads
    cpa_w(W0_OFF, 4);         // G4: W2a (flies under next GEMM)
    gemm1<false>(hacc, hacc, smb + A1_OFF + aoff0, smb + A1_OFF + aoff1, B1, 0);
    __syncthreads();          // all past A0/W1 reads
    {                         // A0 = silu(h + b1)
        __half* dst = (__half*)(sm + A0_OFF);
        POS_LOOP(
            float x = hacc[idx] + __ldg(b1g + col);
            dst[row * 136 + col] = __float2half_rn(x / (1.0f + __expf(-x)));
        )
    }
    cpa_w(W1_OFF, 5);         // G5: W2b
    cpa_w(A1_OFF, 6);         // G6: W2c -> A1+A2 region (dead)
    CP_WAIT0();               // G4, G5, G6 landed
    __syncthreads();

    // ---- phase 3: one triple-B GEMM (a, b, c share the A pass) ----
    float aacc[16], bacc[16], cacc[16];
#pragma unroll
    for (int j = 0; j < 16; j++) { aacc[j] = 0.0f; bacc[j] = 0.0f; cacc[j] = 0.0f; }
    gemm3(aacc, bacc, cacc, smb + A0_OFF + aoff0, smb + A0_OFF + aoff1, B0, B1, B2);

    // ---- epilogue: direct global writes from fragment owners ----
    // delta_s = b + c*dot  (float2, 8B-aligned)
    {
        float* out_ds = out + (size_t)nrows * 384;
#pragma unroll
        for (int mt = 0; mt < 2; mt++)
#pragma unroll
            for (int nt = 0; nt < 2; nt++)
#pragma unroll
                for (int j2 = 0; j2 < 2; j2++) {
                    const int i0 = mt * 8 + nt * 4 + j2 * 2;
                    const int row = rbase + mt * 16 + j2 * 8;
                    const int c = cbase + nt * 8;
                    float c0 = cacc[i0]     + __ldg(b2g + 256 + c);
                    float c1 = cacc[i0 + 1] + __ldg(b2g + 256 + c + 1);
                    float b0v = bacc[i0]     + __ldg(b2g + 128 + c);
                    float b1v = bacc[i0 + 1] + __ldg(b2g + 128 + c + 1);
                    float2 d = make_float2(b0v + c0 * dotv[i0],
                                           b1v + c1 * dotv[i0 + 1]);
                    *(float2*)(out_ds + (size_t)(row0 + row) * 128 + c) = d;
                }
    }
    // delta_v = u (fp32) * a  (3x float2 per (row, col-pair))
#pragma unroll
    for (int mt = 0; mt < 2; mt++)
#pragma unroll
        for (int nt = 0; nt < 2; nt++)
#pragma unroll
            for (int j2 = 0; j2 < 2; j2++) {
                const int i0 = mt * 8 + nt * 4 + j2 * 2;
                const int row = rbase + mt * 16 + j2 * 8;
                const int c = cbase + nt * 8;
                float a0 = aacc[i0]     + __ldg(b2g + c);
                float a1 = aacc[i0 + 1] + __ldg(b2g + c + 1);
                float u0c = Uf[(0 << 13) + (row << 7) + c];
                float u1c = Uf[(1 << 13) + (row << 7) + c];
                float u2c = Uf[(2 << 13) + (row << 7) + c];
                float u0d = Uf[(0 << 13) + (row << 7) + c + 1];
                float u1d = Uf[(1 << 13) + (row << 7) + c + 1];
                float u2d = Uf[(2 << 13) + (row << 7) + c + 1];
                float* op = out + (size_t)(row0 + row) * 384 + (size_t)c * 3;
                ((float2*)op)[0] = make_float2(u0c * a0, u1c * a0);
                ((float2*)op)[1] = make_float2(u2c * a0, u0d * a1);
                ((float2*)op)[2] = make_float2(u1d * a1, u2d * a1);
            }
#undef POS_LOOP
}

// ---------------------------------------------------------------------------
extern "C" void kernel_launch(void* const* d_in, const int* in_sizes, int n_in,
                              void* d_out, int out_size) {
    const float* vec = (const float*)d_in[0];  // [N, C, 3]
    const float* sca = (const float*)d_in[1];  // [N, C]
    const float* U   = (const float*)d_in[2];  // [C, C]
    const float* V   = (const float*)d_in[3];  // [C, C]
    const float* W1  = (const float*)d_in[4];  // [C, 2C]
    const float* b1  = (const float*)d_in[5];  // [C]
    const float* W2  = (const float*)d_in[6];  // [3C, C]
    const float* b2  = (const float*)d_in[7];  // [3C]
    float* out = (float*)d_out;

    int nrows = in_sizes[0] / 384;
    int nblocks = nrows / RB;

    prep_kernel<<<448, 256>>>(U, V, W1, W2);

    cudaFuncSetAttribute(update_mma_kernel,
                         cudaFuncAttributeMaxDynamicSharedMemorySize, SM_TOTAL);
    update_mma_kernel<<<nblocks, NT, SM_TOTAL>>>(vec, sca, b1, b2, out, nrows);
}